// round 16
// baseline (speedup 1.0000x reference)
#include <cuda_runtime.h>
#include <cuda_fp16.h>
#include <math.h>
#include <stdint.h>

#define BB 8
#define CC 192
#define HH 64
#define WW 64
#define NN 4096
#define C4 48
#define CD 194
#define C8 24
#define NKEEP 2048

typedef unsigned long long ull;

// ================= scratch =================
__device__ float g_f[BB*C4*NN];
__device__ float g_off[BB*2*NN];
__device__ float g_score[BB*NN];
__device__ int   g_keep[BB*NKEEP];
__device__ int   g_pos[BB*NN];
__device__ float g_ca[BB*CC];
__device__ float g_sa[BB*NN];
__device__ __align__(16) __half g_xth[(size_t)BB*NN*CC];
__device__ __align__(16) __half g_vth[(size_t)BB*NN*CC];
__device__ __align__(16) __half g_q1h[(size_t)BB*NKEEP*CC];
__device__ __align__(16) __half g_k1h[(size_t)BB*NKEEP*CC];
__device__ __align__(16) __half g_v1th[(size_t)BB*CC*NKEEP];
__device__ __align__(16) __half g_otokTh[(size_t)BB*NN*CC];
__device__ __align__(16) __half g_out2Th[(size_t)BB*NN*CC];

// ================= fp16 mma / ldmatrix / cp.async helpers =================
__device__ __forceinline__ uint32_t f22h2(float x, float y) {
    __half2 h = __floats2half2_rn(x, y);
    return *reinterpret_cast<uint32_t*>(&h);
}
__device__ __forceinline__ uint2 cvt4h(float4 v) {
    return make_uint2(f22h2(v.x, v.y), f22h2(v.z, v.w));
}
__device__ __forceinline__ void mma_f16(float* d, const uint32_t* a, uint32_t b0, uint32_t b1) {
    asm volatile("mma.sync.aligned.m16n8k16.row.col.f32.f16.f16.f32 "
        "{%0,%1,%2,%3}, {%4,%5,%6,%7}, {%8,%9}, {%0,%1,%2,%3};"
        : "+f"(d[0]), "+f"(d[1]), "+f"(d[2]), "+f"(d[3])
        : "r"(a[0]), "r"(a[1]), "r"(a[2]), "r"(a[3]), "r"(b0), "r"(b1));
}
__device__ __forceinline__ void ldsm_x4(uint32_t* r, uint32_t addr) {
    asm volatile("ldmatrix.sync.aligned.m8n8.x4.shared.b16 {%0,%1,%2,%3}, [%4];"
        : "=r"(r[0]), "=r"(r[1]), "=r"(r[2]), "=r"(r[3]) : "r"(addr));
}
#define CP_ASYNC16(dst, src) \
    asm volatile("cp.async.cg.shared.global [%0], [%1], 16;" :: "r"(dst), "l"(src) : "memory")
#define CP_COMMIT() asm volatile("cp.async.commit_group;" ::: "memory")
#define CP_WAIT0()  asm volatile("cp.async.wait_group 0;" ::: "memory")
#define CP_WAIT1()  asm volatile("cp.async.wait_group 1;" ::: "memory")

#define KP 20
#define AS_SZ (128*KP)
#define BS_SZ (64*KP)

// ================= merged V/Q/K GEMM (A fp16 at rest) =================
__global__ void __launch_bounds__(256, 2) k_gemm3(
    const float* __restrict__ v_w, const float* __restrict__ v_b,
    const float* __restrict__ q_w, const float* __restrict__ q_b,
    const float* __restrict__ k_w, const float* __restrict__ k_b,
    float qscale)
{
    int yy = blockIdx.y;
    int op = yy / 3;
    if (op > 0 && blockIdx.x >= 16) return;
    int n0 = (yy % 3) * 64;
    const float* Bw   = (op == 0) ? v_w : (op == 1 ? q_w : k_w);
    const float* bias = (op == 0) ? v_b : (op == 1 ? q_b : k_b);
    float scale = (op == 1) ? qscale : 1.0f;
    const int K = CC;

    extern __shared__ uint32_t sm[];
    uint32_t* As = sm;
    uint32_t* Bs = sm + 2*AS_SZ;
    uint32_t sbase = (uint32_t)__cvta_generic_to_shared(sm);
    int tid = threadIdx.x;
    int lane = tid & 31, wid = tid >> 5;
    int wm = wid & 3, wn = wid >> 2;
    int g = lane >> 2, t4 = lane & 3;
    int la_row = lane & 15, la_kw = (lane >> 4) << 2;
    int lb_row = ((lane >> 4) & 1) * 8 + (lane & 7), lb_kw = ((lane >> 3) & 1) << 2;
    int b = blockIdx.z;
    int m0 = blockIdx.x * 128;

    const __half* Abh = g_xth + (size_t)b * NN * CC;

    const __half* aptr[2];
    const __half* nph[2][4];
    float4 wt4[2];
    int ar[2], ac[2];
    #pragma unroll
    for (int i = 0; i < 2; i++) {
        int idx = tid + i*256;
        ar[i] = idx >> 2; ac[i] = (idx & 3) << 3;
        int grow = (op >= 1) ? g_keep[b*NKEEP + m0 + ar[i]] : (m0 + ar[i]);
        aptr[i] = Abh + (size_t)grow * K + ac[i];
        if (op == 2) {
            const float* offb = g_off + (size_t)(b*2)*NN;
            float sx = (float)(grow & 63) + offb[grow];
            float sy = (float)(grow >> 6) + offb[NN + grow];
            float x0f = floorf(sx), y0f = floorf(sy);
            float wx = sx - x0f, wy = sy - y0f;
            int x0 = (int)x0f, y0 = (int)y0f;
            float* wtp = (float*)&wt4[i];
            #pragma unroll
            for (int j = 0; j < 4; j++) {
                int xi = x0 + (j & 1), yi = y0 + (j >> 1);
                bool valid = (xi >= 0) && (xi <= 63) && (yi >= 0) && (yi <= 63);
                int xc = min(max(xi, 0), 63), yc = min(max(yi, 0), 63);
                float wt = ((j & 1) ? wx : 1.f - wx) * ((j >> 1) ? wy : 1.f - wy);
                wtp[j] = valid ? wt : 0.f;
                nph[i][j] = Abh + (size_t)(yc*64 + xc) * K + ac[i];
            }
        }
    }
    const float* bptr[2];
    int br[2], bc[2];
    #pragma unroll
    for (int i = 0; i < 2; i++) {
        int idx = tid + i*256;
        br[i] = idx >> 3; bc[i] = (idx & 7) << 2;
        bptr[i] = Bw + (size_t)(n0 + br[i]) * K + bc[i];
    }

    float acc[2][4][4];
    #pragma unroll
    for (int mt = 0; mt < 2; mt++)
        #pragma unroll
        for (int nt = 0; nt < 4; nt++)
            #pragma unroll
            for (int e = 0; e < 4; e++) acc[mt][nt][e] = 0.f;

    uint4 pa[2];
    float4 pb[2];
    #pragma unroll
    for (int i = 0; i < 2; i++) pa[i] = *(const uint4*)(aptr[i]);
    #pragma unroll
    for (int i = 0; i < 2; i++) pb[i] = *(const float4*)(bptr[i]);

    #pragma unroll
    for (int i = 0; i < 2; i++) {
        uint4 raw = pa[i];
        if (op == 2) {
            float2 v[4];
            uint32_t* rw = (uint32_t*)&raw;
            #pragma unroll
            for (int wd = 0; wd < 4; wd++) v[wd] = __half22float2(*(__half2*)&rw[wd]);
            const float* wtp = (const float*)&wt4[i];
            #pragma unroll
            for (int j = 0; j < 4; j++) {
                uint4 nr = *(const uint4*)(nph[i][j]);
                uint32_t* nw = (uint32_t*)&nr;
                #pragma unroll
                for (int wd = 0; wd < 4; wd++) {
                    float2 nv = __half22float2(*(__half2*)&nw[wd]);
                    v[wd].x += wtp[j]*nv.x; v[wd].y += wtp[j]*nv.y;
                }
            }
            #pragma unroll
            for (int wd = 0; wd < 4; wd++) rw[wd] = f22h2(v[wd].x, v[wd].y);
        }
        *(uint4*)(As + ar[i]*KP + (ac[i] >> 1)) = raw;
    }
    #pragma unroll
    for (int i = 0; i < 2; i++) *(uint2*)(Bs + br[i]*KP + (bc[i] >> 1)) = cvt4h(pb[i]);
    __syncthreads();

    int nkt = K >> 5;
    for (int kt = 0; kt < nkt; kt++) {
        int buf = kt & 1;
        int off = (kt + 1) << 5;
        if (kt + 1 < nkt) {
            #pragma unroll
            for (int i = 0; i < 2; i++) pa[i] = *(const uint4*)(aptr[i] + off);
            #pragma unroll
            for (int i = 0; i < 2; i++) pb[i] = *(const float4*)(bptr[i] + off);
        }
        uint32_t sbA = sbase + (buf*AS_SZ)*4;
        uint32_t sbB = sbase + (2*AS_SZ + buf*BS_SZ)*4;
        #pragma unroll
        for (int ks = 0; ks < 2; ks++) {
            int k0 = ks*8;
            uint32_t af[2][4], bf[2][4];
            ldsm_x4(af[0], sbA + ((wm*32 +      la_row)*KP + k0 + la_kw)*4);
            ldsm_x4(af[1], sbA + ((wm*32 + 16 + la_row)*KP + k0 + la_kw)*4);
            ldsm_x4(bf[0], sbB + ((wn*32 +      lb_row)*KP + k0 + lb_kw)*4);
            ldsm_x4(bf[1], sbB + ((wn*32 + 16 + lb_row)*KP + k0 + lb_kw)*4);
            #pragma unroll
            for (int nt = 0; nt < 4; nt++) {
                uint32_t b0 = bf[nt>>1][(nt&1)*2], b1 = bf[nt>>1][(nt&1)*2+1];
                mma_f16(acc[0][nt], af[0], b0, b1);
                mma_f16(acc[1][nt], af[1], b0, b1);
            }
        }
        if (kt + 1 < nkt) {
            uint32_t* Asn = As + (buf^1)*AS_SZ;
            uint32_t* Bsn = Bs + (buf^1)*BS_SZ;
            #pragma unroll
            for (int i = 0; i < 2; i++) {
                uint4 raw = pa[i];
                if (op == 2) {
                    float2 v[4];
                    uint32_t* rw = (uint32_t*)&raw;
                    #pragma unroll
                    for (int wd = 0; wd < 4; wd++) v[wd] = __half22float2(*(__half2*)&rw[wd]);
                    const float* wtp = (const float*)&wt4[i];
                    #pragma unroll
                    for (int j = 0; j < 4; j++) {
                        uint4 nr = *(const uint4*)(nph[i][j] + off);
                        uint32_t* nw = (uint32_t*)&nr;
                        #pragma unroll
                        for (int wd = 0; wd < 4; wd++) {
                            float2 nv = __half22float2(*(__half2*)&nw[wd]);
                            v[wd].x += wtp[j]*nv.x; v[wd].y += wtp[j]*nv.y;
                        }
                    }
                    #pragma unroll
                    for (int wd = 0; wd < 4; wd++) rw[wd] = f22h2(v[wd].x, v[wd].y);
                }
                *(uint4*)(Asn + ar[i]*KP + (ac[i] >> 1)) = raw;
            }
            #pragma unroll
            for (int i = 0; i < 2; i++) *(uint2*)(Bsn + br[i]*KP + (bc[i] >> 1)) = cvt4h(pb[i]);
        }
        __syncthreads();
    }

    if (op == 0) {
        __half* Ob = g_vth + (size_t)b * NN * CC;
        __half* V1 = g_v1th + (size_t)b * CC * NKEEP;
        int pos[2][2];
        #pragma unroll
        for (int mt = 0; mt < 2; mt++) {
            pos[mt][0] = g_pos[b*NN + m0 + wm*32 + mt*16 + g];
            pos[mt][1] = g_pos[b*NN + m0 + wm*32 + mt*16 + g + 8];
        }
        #pragma unroll
        for (int nt = 0; nt < 4; nt++) {
            int ncol = n0 + wn*32 + nt*8 + 2*t4;
            float b0v = bias[ncol];
            float b1v = bias[ncol + 1];
            #pragma unroll
            for (int mt = 0; mt < 2; mt++) {
                int row0 = m0 + wm*32 + mt*16 + g;
                float2 o0 = make_float2(acc[mt][nt][0] + b0v, acc[mt][nt][1] + b1v);
                float2 o1 = make_float2(acc[mt][nt][2] + b0v, acc[mt][nt][3] + b1v);
                uint32_t h0 = f22h2(o0.x, o0.y);
                uint32_t h1 = f22h2(o1.x, o1.y);
                *(uint32_t*)&Ob[(size_t)row0 * CC + ncol]     = h0;
                *(uint32_t*)&Ob[(size_t)(row0+8) * CC + ncol] = h1;
                if (pos[mt][0] >= 0) {
                    V1[(size_t)ncol*NKEEP + pos[mt][0]]     = __float2half_rn(o0.x);
                    V1[(size_t)(ncol+1)*NKEEP + pos[mt][0]] = __float2half_rn(o0.y);
                }
                if (pos[mt][1] >= 0) {
                    V1[(size_t)ncol*NKEEP + pos[mt][1]]     = __float2half_rn(o1.x);
                    V1[(size_t)(ncol+1)*NKEEP + pos[mt][1]] = __float2half_rn(o1.y);
                }
            }
        }
    } else {
        __half* Obh = ((op == 1) ? g_q1h : g_k1h) + (size_t)b * NKEEP * CC;
        #pragma unroll
        for (int nt = 0; nt < 4; nt++) {
            int ncol = n0 + wn*32 + nt*8 + 2*t4;
            float b0v = bias[ncol];
            float b1v = bias[ncol + 1];
            #pragma unroll
            for (int mt = 0; mt < 2; mt++) {
                int row0 = m0 + wm*32 + mt*16 + g;
                *(uint32_t*)&Obh[(size_t)row0 * CC + ncol] =
                    f22h2((acc[mt][nt][0] + b0v) * scale, (acc[mt][nt][1] + b1v) * scale);
                *(uint32_t*)&Obh[(size_t)(row0+8) * CC + ncol] =
                    f22h2((acc[mt][nt][2] + b0v) * scale, (acc[mt][nt][3] + b1v) * scale);
            }
        }
    }
}

// ================= final out GEMM (A fp16, transposed epilogue) =================
__global__ void __launch_bounds__(256, 2) k_gemmO(
    const float* __restrict__ Bm,
    const float* __restrict__ bias,
    float* __restrict__ Out)
{
    const int K = CC;
    extern __shared__ uint32_t sm[];
    uint32_t* As = sm;
    uint32_t* Bs = sm + 2*AS_SZ;
    uint32_t sbase = (uint32_t)__cvta_generic_to_shared(sm);
    int tid = threadIdx.x;
    int lane = tid & 31, wid = tid >> 5;
    int wm = wid & 3, wn = wid >> 2;
    int g = lane >> 2, t4 = lane & 3;
    int la_row = lane & 15, la_kw = (lane >> 4) << 2;
    int lb_row = ((lane >> 4) & 1) * 8 + (lane & 7), lb_kw = ((lane >> 3) & 1) << 2;
    int b = blockIdx.z;
    int m0 = blockIdx.x * 128, n0 = blockIdx.y * 64;

    const __half* Abh = g_out2Th + (size_t)b * NN * CC;

    const __half* aptr[2];
    int ar[2], ac[2];
    #pragma unroll
    for (int i = 0; i < 2; i++) {
        int idx = tid + i*256;
        ar[i] = idx >> 2; ac[i] = (idx & 3) << 3;
        aptr[i] = Abh + (size_t)(m0 + ar[i]) * K + ac[i];
    }
    const float* bptr[2];
    int br[2], bc[2];
    #pragma unroll
    for (int i = 0; i < 2; i++) {
        int idx = tid + i*256;
        br[i] = idx >> 3; bc[i] = (idx & 7) << 2;
        bptr[i] = Bm + (size_t)(n0 + br[i]) * K + bc[i];
    }

    float acc[2][4][4];
    #pragma unroll
    for (int mt = 0; mt < 2; mt++)
        #pragma unroll
        for (int nt = 0; nt < 4; nt++)
            #pragma unroll
            for (int e = 0; e < 4; e++) acc[mt][nt][e] = 0.f;

    uint4 pa[2];
    float4 pb[2];
    #pragma unroll
    for (int i = 0; i < 2; i++) pa[i] = *(const uint4*)(aptr[i]);
    #pragma unroll
    for (int i = 0; i < 2; i++) pb[i] = *(const float4*)(bptr[i]);
    #pragma unroll
    for (int i = 0; i < 2; i++) *(uint4*)(As + ar[i]*KP + (ac[i] >> 1)) = pa[i];
    #pragma unroll
    for (int i = 0; i < 2; i++) *(uint2*)(Bs + br[i]*KP + (bc[i] >> 1)) = cvt4h(pb[i]);
    __syncthreads();

    int nkt = K >> 5;
    for (int kt = 0; kt < nkt; kt++) {
        int buf = kt & 1;
        int off = (kt + 1) << 5;
        if (kt + 1 < nkt) {
            #pragma unroll
            for (int i = 0; i < 2; i++) pa[i] = *(const uint4*)(aptr[i] + off);
            #pragma unroll
            for (int i = 0; i < 2; i++) pb[i] = *(const float4*)(bptr[i] + off);
        }
        uint32_t sbA = sbase + (buf*AS_SZ)*4;
        uint32_t sbB = sbase + (2*AS_SZ + buf*BS_SZ)*4;
        #pragma unroll
        for (int ks = 0; ks < 2; ks++) {
            int k0 = ks*8;
            uint32_t af[2][4], bf[2][4];
            ldsm_x4(af[0], sbA + ((wm*32 +      la_row)*KP + k0 + la_kw)*4);
            ldsm_x4(af[1], sbA + ((wm*32 + 16 + la_row)*KP + k0 + la_kw)*4);
            ldsm_x4(bf[0], sbB + ((wn*32 +      lb_row)*KP + k0 + lb_kw)*4);
            ldsm_x4(bf[1], sbB + ((wn*32 + 16 + lb_row)*KP + k0 + lb_kw)*4);
            #pragma unroll
            for (int nt = 0; nt < 4; nt++) {
                uint32_t b0 = bf[nt>>1][(nt&1)*2], b1 = bf[nt>>1][(nt&1)*2+1];
                mma_f16(acc[0][nt], af[0], b0, b1);
                mma_f16(acc[1][nt], af[1], b0, b1);
            }
        }
        if (kt + 1 < nkt) {
            uint32_t* Asn = As + (buf^1)*AS_SZ;
            uint32_t* Bsn = Bs + (buf^1)*BS_SZ;
            #pragma unroll
            for (int i = 0; i < 2; i++) *(uint4*)(Asn + ar[i]*KP + (ac[i] >> 1)) = pa[i];
            #pragma unroll
            for (int i = 0; i < 2; i++) *(uint2*)(Bsn + br[i]*KP + (bc[i] >> 1)) = cvt4h(pb[i]);
        }
        __syncthreads();
    }

    float* st = (float*)sm;
    __syncthreads();
    #pragma unroll
    for (int nt = 0; nt < 4; nt++) {
        int nl = wn*32 + nt*8 + 2*t4;
        float b0v = bias[n0 + nl];
        float b1v = bias[n0 + nl + 1];
        #pragma unroll
        for (int mt = 0; mt < 2; mt++) {
            int ml = wm*32 + mt*16 + g;
            st[nl*132 + ml]         = acc[mt][nt][0] + b0v;
            st[(nl+1)*132 + ml]     = acc[mt][nt][1] + b1v;
            st[nl*132 + ml + 8]     = acc[mt][nt][2] + b0v;
            st[(nl+1)*132 + ml + 8] = acc[mt][nt][3] + b1v;
        }
    }
    __syncthreads();
    for (int l = tid; l < 64*32; l += 256) {
        int r = l >> 5, c4v = (l & 31) << 2;
        float4 v = *(float4*)&st[r*132 + c4v];
        *(float4*)&Out[((size_t)b*CC + n0 + r)*NN + m0 + c4v] = v;
    }
}

// ================= flash attention: 64q tiles, Q-in-regs, 2 CTAs/SM =============
#define F_KS 0                 // K 2 x (64 x 100)
#define F_VS 12800             // V 192 x 36 (single)
#define F_PS 19712             // Ps 64 x 36
#define F_PM 22016             // pmx 64 x 2
#define F_SUM 22144            // psum 64 x 2
#define F_MST 22272
#define F_LST 22336
#define F_SCL 22400
#define F_TOT 22464
#define NTILES (NKEEP/64)

__global__ void __launch_bounds__(256, 2) k_flash() {
    extern __shared__ uint32_t sm[];
    uint32_t* Ksm = sm + F_KS;
    uint32_t* Vsm = sm + F_VS;
    uint32_t* Ps = sm + F_PS;
    float* pmx = (float*)(sm + F_PM);
    float* psum = (float*)(sm + F_SUM);
    float* mst = (float*)(sm + F_MST);
    float* lst = (float*)(sm + F_LST);
    float* scl = (float*)(sm + F_SCL);
    uint32_t sbase = (uint32_t)__cvta_generic_to_shared(sm);

    int tid = threadIdx.x, lane = tid & 31, w = tid >> 5;
    int g = lane >> 2, t4 = lane & 3;
    int la_row = lane & 15, la_kw = (lane >> 4) << 2;
    int lb_row = ((lane >> 4) & 1) * 8 + (lane & 7), lb_kw = ((lane >> 3) & 1) << 2;
    int b = blockIdx.y, m0 = blockIdx.x * 64;

    const __half* Qg = g_q1h + ((size_t)b*NKEEP + m0)*CC;
    const __half* Kg = g_k1h + (size_t)b*NKEEP*CC;
    const __half* Vg = g_v1th + (size_t)b*CC*NKEEP;

    int iq = w >> 1, jk = w & 1;   // QK: 4 q-tiles x 2 key halves
    int qr0 = iq * 16;
    int wm = w & 3, wn = w >> 2;   // PV: 4 ch-groups(48) x 2 q-groups(32)

    // --- prologue: stage Q via K buf0, ldsm to registers ---
    #pragma unroll
    for (int j = 0; j < 6; j++) {
        int idx = tid + j*256;
        int r = idx/24, ch = idx%24;
        *(uint4*)&Ksm[r*100 + ch*4] = *(const uint4*)(Qg + (size_t)r*CC + ch*8);
    }
    __syncthreads();
    uint32_t qf[12][4];
    #pragma unroll
    for (int ks = 0; ks < 12; ks++)
        ldsm_x4(qf[ks], sbase + (F_KS + (qr0 + la_row)*100 + ks*8 + la_kw)*4);
    if (tid < 64) { mst[tid] = -1e30f; lst[tid] = 0.f; }
    __syncthreads();   // Q reads done before K_0 overwrites buf0

    // per-thread cp.async coordinates (K 64x24 chunks, V 192x8 chunks; 6 each)
    int rK[6], cKc[6], rV[6], cVc[6];
    #pragma unroll
    for (int j = 0; j < 6; j++) {
        int idx = tid + j*256;
        rK[j] = idx/24; cKc[j] = idx%24;
        rV[j] = idx/8;  cVc[j] = idx%8;
    }
    // K_0 / V_0
    #pragma unroll
    for (int j = 0; j < 6; j++) {
        CP_ASYNC16(sbase + (F_KS + rK[j]*100 + cKc[j]*4)*4,
                   Kg + (size_t)rK[j]*CC + cKc[j]*8);
        CP_ASYNC16(sbase + (F_VS + rV[j]*36 + cVc[j]*4)*4,
                   Vg + (size_t)rV[j]*NKEEP + cVc[j]*8);
    }
    CP_COMMIT();
    CP_WAIT0();
    __syncthreads();

    float oat[3][4][4];
    #pragma unroll
    for (int mt = 0; mt < 3; mt++)
        #pragma unroll
        for (int nt = 0; nt < 4; nt++)
            #pragma unroll
            for (int e = 0; e < 4; e++) oat[mt][nt][e] = 0.f;

    #pragma unroll 1
    for (int kt = 0; kt < NTILES; kt++) {
        int buf = kt & 1;
        // ---- QK: 16q x 32k per warp, Q from registers ----
        float sacc[4][4];
        #pragma unroll
        for (int nt = 0; nt < 4; nt++)
            #pragma unroll
            for (int e = 0; e < 4; e++) sacc[nt][e] = 0.f;
        #pragma unroll
        for (int ks = 0; ks < 12; ks++) {
            int k0 = ks*8;
            uint32_t bf[2][4];
            ldsm_x4(bf[0], sbase + (F_KS + buf*6400 + (jk*32 +      lb_row)*100 + k0 + lb_kw)*4);
            ldsm_x4(bf[1], sbase + (F_KS + buf*6400 + (jk*32 + 16 + lb_row)*100 + k0 + lb_kw)*4);
            mma_f16(sacc[0], qf[ks], bf[0][0], bf[0][1]);
            mma_f16(sacc[1], qf[ks], bf[0][2], bf[0][3]);
            mma_f16(sacc[2], qf[ks], bf[1][0], bf[1][1]);
            mma_f16(sacc[3], qf[ks], bf[1][2], bf[1][3]);
        }
        // ---- partial row max ----
        float mx0 = -1e30f, mx1 = -1e30f;
        #pragma unroll
        for (int nt = 0; nt < 4; nt++) {
            mx0 = fmaxf(mx0, fmaxf(sacc[nt][0], sacc[nt][1]));
            mx1 = fmaxf(mx1, fmaxf(sacc[nt][2], sacc[nt][3]));
        }
        mx0 = fmaxf(mx0, __shfl_xor_sync(~0u, mx0, 1));
        mx0 = fmaxf(mx0, __shfl_xor_sync(~0u, mx0, 2));
        mx1 = fmaxf(mx1, __shfl_xor_sync(~0u, mx1, 1));
        mx1 = fmaxf(mx1, __shfl_xor_sync(~0u, mx1, 2));
        if (t4 == 0) {
            pmx[(qr0+g)*2 + jk]   = mx0;
            pmx[(qr0+g+8)*2 + jk] = mx1;
        }
        __syncthreads();   // S1: pmx visible; K_kt reads done
        // issue K_{kt+1}
        if (kt + 1 < NTILES) {
            int k0n = (kt + 1) * 64;
            #pragma unroll
            for (int j = 0; j < 6; j++)
                CP_ASYNC16(sbase + (F_KS + (buf^1)*6400 + rK[j]*100 + cKc[j]*4)*4,
                           Kg + (size_t)(k0n + rK[j])*CC + cKc[j]*8);
            CP_COMMIT();
        }
        // ---- phase C: exp + partial sums + P ----
        float mo0 = mst[qr0+g], mo1 = mst[qr0+g+8];
        float mn0 = fmaxf(mo0, fmaxf(pmx[(qr0+g)*2],   pmx[(qr0+g)*2+1]));
        float mn1 = fmaxf(mo1, fmaxf(pmx[(qr0+g+8)*2], pmx[(qr0+g+8)*2+1]));
        float s0 = 0.f, s1 = 0.f;
        #pragma unroll
        for (int nt = 0; nt < 4; nt++) {
            float e00 = __expf(sacc[nt][0] - mn0);
            float e01 = __expf(sacc[nt][1] - mn0);
            float e10 = __expf(sacc[nt][2] - mn1);
            float e11 = __expf(sacc[nt][3] - mn1);
            s0 += e00 + e01; s1 += e10 + e11;
            Ps[(qr0+g)*36   + jk*16 + nt*4 + t4] = f22h2(e00, e01);
            Ps[(qr0+g+8)*36 + jk*16 + nt*4 + t4] = f22h2(e10, e11);
        }
        s0 += __shfl_xor_sync(~0u, s0, 1); s0 += __shfl_xor_sync(~0u, s0, 2);
        s1 += __shfl_xor_sync(~0u, s1, 1); s1 += __shfl_xor_sync(~0u, s1, 2);
        if (t4 == 0) {
            psum[(qr0+g)*2 + jk]   = s0;
            psum[(qr0+g+8)*2 + jk] = s1;
        }
        __syncthreads();   // S2: Ps/psum visible
        if (tid < 64) {
            float pmF = fmaxf(pmx[tid*2], pmx[tid*2+1]);
            float mo = mst[tid];
            float mn = fmaxf(mo, pmF);
            float al = __expf(mo - mn);
            lst[tid] = lst[tid]*al + psum[tid*2] + psum[tid*2+1];
            mst[tid] = mn;
            scl[tid] = al;
        }
        CP_WAIT1();        // V_kt complete (older than K_{kt+1}); no-op at kt=0
        __syncthreads();   // S3: scl + V visible
        // ---- PV: rescale + O^T += V^T P^T over 64 keys ----
        #pragma unroll
        for (int nt = 0; nt < 4; nt++) {
            int qc = wn*32 + nt*8 + 2*t4;
            float a0 = scl[qc], a1 = scl[qc+1];
            #pragma unroll
            for (int mt = 0; mt < 3; mt++) {
                oat[mt][nt][0] *= a0; oat[mt][nt][1] *= a1;
                oat[mt][nt][2] *= a0; oat[mt][nt][3] *= a1;
            }
        }
        #pragma unroll
        for (int ks = 0; ks < 4; ks++) {
            int k0 = ks*8;
            uint32_t pf[2][4];
            ldsm_x4(pf[0], sbase + (F_PS + (wn*32 +      lb_row)*36 + k0 + lb_kw)*4);
            ldsm_x4(pf[1], sbase + (F_PS + (wn*32 + 16 + lb_row)*36 + k0 + lb_kw)*4);
            #pragma unroll
            for (int mt = 0; mt < 3; mt++) {
                int cr = wm*48 + mt*16;
                uint32_t a[4];
                ldsm_x4(a, sbase + (F_VS + (cr + la_row)*36 + k0 + la_kw)*4);
                #pragma unroll
                for (int nt = 0; nt < 4; nt++)
                    mma_f16(oat[mt][nt], a, pf[nt>>1][(nt&1)*2], pf[nt>>1][(nt&1)*2+1]);
            }
        }
        __syncthreads();   // S4: V_kt reads done (protect single V buffer)
        if (kt + 1 < NTILES) {
            int k0n = (kt + 1) * 64;
            #pragma unroll
            for (int j = 0; j < 6; j++)
                CP_ASYNC16(sbase + (F_VS + rV[j]*36 + cVc[j]*4)*4,
                           Vg + (size_t)rV[j]*NKEEP + k0n + cVc[j]*8);
            CP_COMMIT();
        }
        CP_WAIT1();        // K_{kt+1} complete (older than V_{kt+1})
        __syncthreads();   // S5: K visible for next QK
    }

    // ---- epilogue: normalize, transpose via smem, fp16 scatter ----
    float* Ot = (float*)sm;   // [64][196] = 12544 w; state arrays at 22016+ remain safe
    #pragma unroll
    for (int nt = 0; nt < 4; nt++) {
        int qc = wn*32 + nt*8 + 2*t4;
        float li0 = 1.f / lst[qc], li1 = 1.f / lst[qc+1];
        #pragma unroll
        for (int mt = 0; mt < 3; mt++) {
            int cr = wm*48 + mt*16;
            Ot[qc*196 + cr+g]       = oat[mt][nt][0] * li0;
            Ot[(qc+1)*196 + cr+g]   = oat[mt][nt][1] * li1;
            Ot[qc*196 + cr+g+8]     = oat[mt][nt][2] * li0;
            Ot[(qc+1)*196 + cr+g+8] = oat[mt][nt][3] * li1;
        }
    }
    __syncthreads();
    #pragma unroll
    for (int j = 0; j < 12; j++) {
        int idx = tid + j*256;
        int r = idx/48, c4v = (idx%48)*4;
        int tok = g_keep[b*NKEEP + m0 + r];
        float4 v = *(float4*)&Ot[r*196 + c4v];
        uint2 h = cvt4h(v);
        *(uint2*)&g_otokTh[((size_t)b*NN + tok)*CC + c4v] = h;
    }
}

// ================= front end (+ fused fp16 x transpose) =================
__global__ void k_front(const float* __restrict__ x,
    const float* __restrict__ in_w, const float* __restrict__ in_b,
    const float* __restrict__ ln_w, const float* __restrict__ ln_b,
    const float* __restrict__ ow1, const float* __restrict__ ob1,
    const float* __restrict__ ow2, const float* __restrict__ ob2,
    const float* __restrict__ mw1, const float* __restrict__ mb1,
    const float* __restrict__ mw2, const float* __restrict__ mb2)
{
    __shared__ float cond[CD][33];
    __shared__ float fb[C4][33];
    __shared__ float mu_s[32], rs_s[32];
    __shared__ float hb[C8][33];
    int b = blockIdx.y;
    int n0 = blockIdx.x * 32;
    int tid = threadIdx.x;

    for (int l = tid; l < CC*32; l += 256) {
        int c = l >> 5, px = l & 31;
        cond[c][px] = x[((b*CC + c) << 12) + n0 + px];
    }
    if (tid < 32) {
        int n = n0 + tid;
        int h = n >> 6, w = n & 63;
        cond[192][tid] = -1.0f + 2.0f * (float)w / 63.0f;
        cond[193][tid] = -1.0f + 2.0f * (float)h / 63.0f;
    }
    __syncthreads();

    for (int l = tid; l < 32*96; l += 256) {
        int px = l / 96, c2 = (l % 96) * 2;
        *(uint32_t*)&g_xth[((size_t)b*NN + n0 + px)*CC + c2] =
            f22h2(cond[c2][px], cond[c2+1][px]);
    }

    int px = tid & 31;
    for (int pass = 0; pass < 6; pass++) {
        int c = pass*8 + (tid >> 5);
        float acc = in_b[c];
        const float* wr = in_w + c*CD;
        #pragma unroll 2
        for (int k = 0; k < CD; k++) acc += wr[k] * cond[k][px];
        fb[c][px] = acc;
    }
    __syncthreads();

    if (tid < 32) {
        float s = 0.f, s2 = 0.f;
        for (int c = 0; c < C4; c++) { float v = fb[c][tid]; s += v; s2 += v*v; }
        float mu = s / (float)C4;
        float var = s2 / (float)C4 - mu*mu;
        mu_s[tid] = mu;
        rs_s[tid] = rsqrtf(var + 1e-6f);
    }
    __syncthreads();

    for (int l = tid; l < C4*32; l += 256) {
        int c = l >> 5, p = l & 31;
        float v = (fb[c][p] - mu_s[p]) * rs_s[p] * ln_w[c] + ln_b[c];
        v = v > 0.f ? v : 0.1f*v;
        fb[c][p] = v;
        g_f[(b*C4 + c)*NN + n0 + p] = v;
    }
    __syncthreads();

    for (int l = tid; l < C8*32; l += 256) {
        int j = l >> 5, p = l & 31;
        float acc = ob1[j];
        const float* wr = ow1 + j*C4;
        #pragma unroll 4
        for (int c = 0; c < C4; c++) acc += wr[c] * fb[c][p];
        hb[j][p] = acc > 0.f ? acc : 0.1f*acc;
    }
    __syncthreads();

    if (tid < 64) {
        int d = tid >> 5, p = tid & 31;
        float acc = ob2[d];
        const float* wr = ow2 + d*C8;
        #pragma unroll
        for (int j = 0; j < C8; j++) acc += wr[j] * hb[j][p];
        g_off[(b*2 + d)*NN + n0 + p] = tanhf(acc) * 8.0f;
    }
    if (tid >= 64 && tid < 96) {
        int p = tid - 64;
        float s = 0.f;
        for (int c = 0; c < C4; c++) s += fb[c][p];
        float t = s / (float)C4;
        float s1 = t * mw1[0] + mb1[0];
        s1 = s1 > 0.f ? s1 : 0.1f*s1;
        float l0 = s1 * mw2[0] + mb2[0];
        float l1 = s1 * mw2[1] + mb2[1];
        g_score[b*NN + n0 + p] = 1.0f / (1.0f + expf(l1 - l0));
    }
}

// ================= merged aux: sa (blocks 0-3) | stats + ca + topk (block 4) =====
__device__ __forceinline__ unsigned int ford(float f) {
    unsigned int u = __float_as_uint(f);
    return (u & 0x80000000u) ? ~u : (u | 0x80000000u);
}
__global__ void __launch_bounds__(1024) k_aux(
    const float* __restrict__ caw, const float* __restrict__ cab,
    const float* __restrict__ saw, const float* __restrict__ sab)
{
    extern __shared__ char smaux[];
    int b = blockIdx.y;
    int tid = threadIdx.x;
    int lane = tid & 31, wid = tid >> 5;

    if (blockIdx.x < 4) {
        float* wsh = (float*)smaux;
        float* smf = wsh + C4*9;
        int h0 = blockIdx.x * 16;
        for (int l = tid; l < C4*9; l += 1024) wsh[l] = saw[l];
        int lw = tid & 63, lh = tid >> 6;
        float acc = sab[0];
        const float* fb = g_f + b*C4*NN;
        for (int c = 0; c < C4; c++) {
            __syncthreads();
            for (int l = tid; l < 18*64; l += 1024) {
                int r = l >> 6, ww = l & 63;
                int hh = h0 - 1 + r;
                smf[l] = (hh >= 0 && hh < HH) ? fb[c*NN + hh*64 + ww] : 0.f;
            }
            __syncthreads();
            #pragma unroll
            for (int dh = 0; dh < 3; dh++) {
                float w0 = wsh[c*9+dh*3+0], w1 = wsh[c*9+dh*3+1], w2 = wsh[c*9+dh*3+2];
                const float* row = smf + (lh + dh)*64;
                float vm = (lw > 0)  ? row[lw-1] : 0.f;
                float vc = row[lw];
                float vp = (lw < 63) ? row[lw+1] : 0.f;
                acc += w0*vm + w1*vc + w2*vp;
            }
        }
        g_sa[b*NN + (h0+lh)*64 + lw] = 1.f/(1.f + __expf(-acc));
        return;
    }

    ull* keys  = (ull*)smaux;
    int* hist  = (int*)(smaux + 32768);
    int* scan_ = (int*)(smaux + 33792);
    ull* selp  = (ull*)(smaux + 34816);
    int* selk  = (int*)(smaux + 34824);
    int* wsum  = (int*)(smaux + 34832);
    float* fm  = (float*)(smaux + 34960);

    for (int c = wid; c < C4; c += 32) {
        const float* p = g_f + (b*C4 + c)*NN;
        float s = 0.f;
        for (int i = lane; i < NN; i += 32) s += p[i];
        #pragma unroll
        for (int o = 16; o; o >>= 1) s += __shfl_xor_sync(~0u, s, o);
        if (lane == 0) fm[c] = s / (float)NN;
    }
    __syncthreads();
    if (tid < CC) {
        float acc = cab[tid];
        #pragma unroll 4
        for (int c = 0; c < C4; c++) acc += caw[tid*C4 + c] * fm[c];
        g_ca[b*CC + tid] = 1.0f / (1.0f + __expf(-acc));
    }

    for (int l = tid; l < NN; l += 1024) {
        unsigned int o = ford(g_score[b*NN + l]) ^ 0xFFFFFFFFu;
        keys[l] = ((ull)o << 32) | (unsigned int)l;
    }
    if (tid == 0) { selp[0] = 0; selk[0] = NKEEP - 1; }
    __syncthreads();

    const int bseq[6] = {7, 6, 5, 4, 1, 0};
    ull prefix = 0, mask = 0;
    #pragma unroll 1
    for (int bi = 0; bi < 6; bi++) {
        int sh = bseq[bi] * 8;
        if (tid < 256) hist[tid] = 0;
        __syncthreads();
        for (int l = tid; l < NN; l += 1024) {
            ull k = keys[l];
            if ((k & mask) == prefix) atomicAdd(&hist[(int)((k >> sh) & 0xFF)], 1);
        }
        __syncthreads();
        if (tid < 256) scan_[tid] = hist[tid];
        __syncthreads();
        #pragma unroll
        for (int off = 1; off < 256; off <<= 1) {
            int v = 0;
            if (tid < 256 && tid >= off) v = scan_[tid - off];
            __syncthreads();
            if (tid < 256) scan_[tid] += v;
            __syncthreads();
        }
        int kcur = selk[0];
        __syncthreads();
        if (tid < 256) {
            int incl = scan_[tid], excl = incl - hist[tid];
            if (kcur >= excl && kcur < incl) {
                selp[0] = prefix | ((ull)tid << sh);
                selk[0] = kcur - excl;
            }
        }
        __syncthreads();
        prefix = selp[0];
        mask |= (0xFFull << sh);
        __syncthreads();
    }
    ull kstar = prefix;

    int base = tid * 4;
    int kept[4], c = 0;
    #pragma unroll
    for (int j = 0; j < 4; j++) {
        kept[j] = (keys[base + j] <= kstar) ? 1 : 0;
        c += kept[j];
    }
    int incl = c;
    #pragma unroll
    for (int o = 1; o < 32; o <<= 1) {
        int v = __shfl_up_sync(~0u, incl, o);
        if (lane >= o) incl += v;
    }
    if (lane == 31) wsum[wid] = incl;
    __syncthreads();
    if (wid == 0) {
        int v = (lane < 32) ? wsum[lane] : 0;
        #pragma unroll
        for (int o = 1; o < 32; o <<= 1) {
            int u = __shfl_up_sync(~0u, v, o);
            if (lane >= o) v += u;
        }
        wsum[lane] = v;
    }
    __syncthreads();
    int offset = (wid > 0 ? wsum[wid - 1] : 0) + incl - c;
    #pragma unroll
    for (int j = 0; j < 4; j++) {
        int tok = base + j;
        if (kept[j]) {
            g_keep[b*NKEEP + offset] = tok;
            g_pos[b*NN + tok] = offset;
            offset++;
        } else {
            g_pos[b*NN + tok] = -1;
        }
    }
}

// ================= token-major depthwise 3x3 + gelu*ca + residual (fp16 in/out) ====
__global__ void __launch_bounds__(192) k_dwT(const float* __restrict__ csw, const float* __restrict__ csb) {
    extern __shared__ float sdw[];
    float* tile = sdw;
    float* wsm = sdw + 100*192;
    int b = blockIdx.y;
    int t = blockIdx.x;
    int th0 = (t >> 3) * 8, tw0 = (t & 7) * 8;
    int tid = threadIdx.x;
    for (int l = tid; l < 192*9; l += 192) wsm[l] = csw[l];
    const __half* inb = g_otokTh + (size_t)b*NN*CC;
    const __half* vtb = g_vth + (size_t)b*NN*CC;
    for (int l = tid; l < 100*48; l += 192) {
        int pos = l / 48, c4v = (l % 48)*4;
        int hh = th0 - 1 + pos/10, ww = tw0 - 1 + pos%10;
        float4 v = make_float4(0.f, 0.f, 0.f, 0.f);
        if (hh >= 0 && hh < 64 && ww >= 0 && ww < 64) {
            int n = hh*64 + ww;
            uint2 raw;
            if (g_pos[b*NN + n] >= 0) {
                raw = *(const uint2*)(inb + (size_t)n*CC + c4v);
                float2 lo = __half22float2(*(__half2*)&raw.x);
                float2 hi = __half22float2(*(__half2*)&raw.y);
                v = make_float4(lo.x, lo.y, hi.x, hi.y);
            } else {
                raw = *(const uint2*)(vtb + (size_t)n*CC + c4v);
                float2 lo = __half22float2(*(__half2*)&raw.x);
                float2 hi = __half22float2(*(__half2*)&raw.y);
                float s = g_sa[b*NN + n];
                v = make_float4(lo.x*s, lo.y*s, hi.x*s, hi.y*s);
            }
        }
        *(float4*)&tile[pos*192 + c4v] = v;
    }
    __syncthreads();

    int c4 = (tid % 48) * 4;
    int pxb = tid / 48;
    float wreg[9][4];
    #pragma unroll
    for (int tap = 0; tap < 9; tap++)
        #pragma unroll
        for (int e = 0; e < 4; e++)
            wreg[tap][e] = wsm[(c4+e)*9 + tap];
    float bv[4], cav[4];
    #pragma unroll
    for (int e = 0; e < 4; e++) { bv[e] = csb[c4+e]; cav[e] = g_ca[b*CC + c4 + e]; }

    __half* outb = g_out2Th + (size_t)b*NN*CC;
    for (int j = 0; j < 16; j++) {
        int px = pxb*16 + j;
        int lh = px >> 3, lw2 = px & 7;
        float acc[4] = {bv[0], bv[1], bv[2], bv[3]};
        #pragma unroll
        for (int dh = 0; dh < 3; dh++)
            #pragma unroll
            for (int dw_ = 0; dw_ < 3; dw_++) {
                int pos = (lh+dh)*10 + (lw2+dw_);
                float4 v = *(const float4*)&tile[pos*192 + c4];
                int tap = dh*3 + dw_;
                acc[0] += wreg[tap][0]*v.x; acc[1] += wreg[tap][1]*v.y;
                acc[2] += wreg[tap][2]*v.z; acc[3] += wreg[tap][3]*v.w;
            }
        float4 cen = *(const float4*)&tile[((lh+1)*10 + (lw2+1))*192 + c4];
        float* cenp = (float*)&cen;
        float o[4];
        #pragma unroll
        for (int e = 0; e < 4; e++) {
            float a = acc[e];
            float x3 = a*a*a;
            float gg = 0.5f*a*(1.0f + tanhf(0.7978845608028654f*(a + 0.044715f*x3)));
            o[e] = gg * cav[e] + cenp[e];
        }
        int n = (th0+lh)*64 + (tw0+lw2);
        uint2 o2 = make_uint2(f22h2(o[0], o[1]), f22h2(o[2], o[3]));
        *(uint2*)(outb + (size_t)n*CC + c4) = o2;
    }
}

// ================= host =================
extern "C" void kernel_launch(void* const* d_in, const int* in_sizes, int n_in,
                              void* d_out, int out_size) {
    const float* x     = (const float*)d_in[0];
    const float* in_w  = (const float*)d_in[1];
    const float* in_b  = (const float*)d_in[2];
    const float* ln_w  = (const float*)d_in[3];
    const float* ln_b  = (const float*)d_in[4];
    const float* ow1   = (const float*)d_in[5];
    const float* ob1   = (const float*)d_in[6];
    const float* ow2   = (const float*)d_in[7];
    const float* ob2   = (const float*)d_in[8];
    const float* caw   = (const float*)d_in[9];
    const float* cab   = (const float*)d_in[10];
    const float* saw   = (const float*)d_in[11];
    const float* sab   = (const float*)d_in[12];
    const float* mw1   = (const float*)d_in[13];
    const float* mb1   = (const float*)d_in[14];
    const float* mw2   = (const float*)d_in[15];
    const float* mb2   = (const float*)d_in[16];
    const float* v_w   = (const float*)d_in[17];
    const float* v_b   = (const float*)d_in[18];
    const float* q_w   = (const float*)d_in[19];
    const float* q_b   = (const float*)d_in[20];
    const float* k_w   = (const float*)d_in[21];
    const float* k_b   = (const float*)d_in[22];
    const float* cs_w  = (const float*)d_in[23];
    const float* cs_b  = (const float*)d_in[24];
    const float* out_w = (const float*)d_in[25];
    const float* out_b = (const float*)d_in[26];
    float* out = (float*)d_out;

    const int SMEM_G = 8448 * 4;
    cudaFuncSetAttribute(k_gemm3, cudaFuncAttributeMaxDynamicSharedMemorySize, SMEM_G);
    cudaFuncSetAttribute(k_gemmO, cudaFuncAttributeMaxDynamicSharedMemorySize, SMEM_G);
    const int SMEM_F = F_TOT * 4;  // 89856 -> 2 CTAs/SM
    cudaFuncSetAttribute(k_flash, cudaFuncAttributeMaxDynamicSharedMemorySize, SMEM_F);
    const int SMEM_DW = (100*192 + 192*9) * 4;
    cudaFuncSetAttribute(k_dwT, cudaFuncAttributeMaxDynamicSharedMemorySize, SMEM_DW);
    const int SMEM_AUX = 35200;
    cudaFuncSetAttribute(k_aux, cudaFuncAttributeMaxDynamicSharedMemorySize, SMEM_AUX);

    k_front<<<dim3(NN/32, BB), 256>>>(x, in_w, in_b, ln_w, ln_b,
                                      ow1, ob1, ow2, ob2, mw1, mb1, mw2, mb2);
    k_aux<<<dim3(5, BB), 1024, SMEM_AUX>>>(caw, cab, saw, sab);

    float scale = rsqrtf((float)CC);
    k_gemm3<<<dim3(NN/128, 9, BB), 256, SMEM_G>>>(
        v_w, v_b, q_w, q_b, k_w, k_b, scale);
    k_flash<<<dim3(NKEEP/64, BB), 256, SMEM_F>>>();
    k_dwT<<<dim3(64, BB), 192, SMEM_DW>>>(cs_w, cs_b);
    k_gemmO<<<dim3(NN/128, 3, BB), 256, SMEM_G>>>(out_w, out_b, out);
}

// round 17
// speedup vs baseline: 1.0426x; 1.0426x over previous
#include <cuda_runtime.h>
#include <cuda_fp16.h>
#include <math.h>
#include <stdint.h>

#define BB 8
#define CC 192
#define HH 64
#define WW 64
#define NN 4096
#define C4 48
#define CD 194
#define C8 24
#define NKEEP 2048

typedef unsigned long long ull;

// ================= scratch =================
__device__ float g_f[BB*C4*NN];
__device__ float g_off[BB*2*NN];
__device__ float g_score[BB*NN];
__device__ int   g_keep[BB*NKEEP];
__device__ int   g_pos[BB*NN];
__device__ float g_ca[BB*CC];
__device__ float g_sa[BB*NN];
__device__ __align__(16) __half g_xth[(size_t)BB*NN*CC];
__device__ __align__(16) __half g_vth[(size_t)BB*NN*CC];
__device__ __align__(16) __half g_q1h[(size_t)BB*NKEEP*CC];
__device__ __align__(16) __half g_k1h[(size_t)BB*NKEEP*CC];
__device__ __align__(16) __half g_v1th[(size_t)BB*CC*NKEEP];
__device__ __align__(16) __half g_otokTh[(size_t)BB*NN*CC];
__device__ __align__(16) __half g_out2Th[(size_t)BB*NN*CC];

// ================= fp16 mma / ldmatrix / cp.async helpers =================
__device__ __forceinline__ uint32_t f22h2(float x, float y) {
    __half2 h = __floats2half2_rn(x, y);
    return *reinterpret_cast<uint32_t*>(&h);
}
__device__ __forceinline__ uint2 cvt4h(float4 v) {
    return make_uint2(f22h2(v.x, v.y), f22h2(v.z, v.w));
}
__device__ __forceinline__ void mma_f16(float* d, const uint32_t* a, uint32_t b0, uint32_t b1) {
    asm volatile("mma.sync.aligned.m16n8k16.row.col.f32.f16.f16.f32 "
        "{%0,%1,%2,%3}, {%4,%5,%6,%7}, {%8,%9}, {%0,%1,%2,%3};"
        : "+f"(d[0]), "+f"(d[1]), "+f"(d[2]), "+f"(d[3])
        : "r"(a[0]), "r"(a[1]), "r"(a[2]), "r"(a[3]), "r"(b0), "r"(b1));
}
__device__ __forceinline__ void ldsm_x4(uint32_t* r, uint32_t addr) {
    asm volatile("ldmatrix.sync.aligned.m8n8.x4.shared.b16 {%0,%1,%2,%3}, [%4];"
        : "=r"(r[0]), "=r"(r[1]), "=r"(r[2]), "=r"(r[3]) : "r"(addr));
}
#define CP_ASYNC16(dst, src) \
    asm volatile("cp.async.cg.shared.global [%0], [%1], 16;" :: "r"(dst), "l"(src) : "memory")
#define CP_COMMIT() asm volatile("cp.async.commit_group;" ::: "memory")
#define CP_WAIT0()  asm volatile("cp.async.wait_group 0;" ::: "memory")

#define KP 20
#define AS_SZ (128*KP)
#define BS_SZ (64*KP)

// ================= merged V/Q/K GEMM (A fp16 at rest) =================
__global__ void __launch_bounds__(256, 2) k_gemm3(
    const float* __restrict__ v_w, const float* __restrict__ v_b,
    const float* __restrict__ q_w, const float* __restrict__ q_b,
    const float* __restrict__ k_w, const float* __restrict__ k_b,
    float qscale)
{
    int yy = blockIdx.y;
    int op = yy / 3;
    if (op > 0 && blockIdx.x >= 16) return;
    int n0 = (yy % 3) * 64;
    const float* Bw   = (op == 0) ? v_w : (op == 1 ? q_w : k_w);
    const float* bias = (op == 0) ? v_b : (op == 1 ? q_b : k_b);
    float scale = (op == 1) ? qscale : 1.0f;
    const int K = CC;

    extern __shared__ uint32_t sm[];
    uint32_t* As = sm;
    uint32_t* Bs = sm + 2*AS_SZ;
    uint32_t sbase = (uint32_t)__cvta_generic_to_shared(sm);
    int tid = threadIdx.x;
    int lane = tid & 31, wid = tid >> 5;
    int wm = wid & 3, wn = wid >> 2;
    int g = lane >> 2, t4 = lane & 3;
    int la_row = lane & 15, la_kw = (lane >> 4) << 2;
    int lb_row = ((lane >> 4) & 1) * 8 + (lane & 7), lb_kw = ((lane >> 3) & 1) << 2;
    int b = blockIdx.z;
    int m0 = blockIdx.x * 128;

    const __half* Abh = g_xth + (size_t)b * NN * CC;

    const __half* aptr[2];
    const __half* nph[2][4];
    float4 wt4[2];
    int ar[2], ac[2];
    #pragma unroll
    for (int i = 0; i < 2; i++) {
        int idx = tid + i*256;
        ar[i] = idx >> 2; ac[i] = (idx & 3) << 3;
        int grow = (op >= 1) ? g_keep[b*NKEEP + m0 + ar[i]] : (m0 + ar[i]);
        aptr[i] = Abh + (size_t)grow * K + ac[i];
        if (op == 2) {
            const float* offb = g_off + (size_t)(b*2)*NN;
            float sx = (float)(grow & 63) + offb[grow];
            float sy = (float)(grow >> 6) + offb[NN + grow];
            float x0f = floorf(sx), y0f = floorf(sy);
            float wx = sx - x0f, wy = sy - y0f;
            int x0 = (int)x0f, y0 = (int)y0f;
            float* wtp = (float*)&wt4[i];
            #pragma unroll
            for (int j = 0; j < 4; j++) {
                int xi = x0 + (j & 1), yi = y0 + (j >> 1);
                bool valid = (xi >= 0) && (xi <= 63) && (yi >= 0) && (yi <= 63);
                int xc = min(max(xi, 0), 63), yc = min(max(yi, 0), 63);
                float wt = ((j & 1) ? wx : 1.f - wx) * ((j >> 1) ? wy : 1.f - wy);
                wtp[j] = valid ? wt : 0.f;
                nph[i][j] = Abh + (size_t)(yc*64 + xc) * K + ac[i];
            }
        }
    }
    const float* bptr[2];
    int br[2], bc[2];
    #pragma unroll
    for (int i = 0; i < 2; i++) {
        int idx = tid + i*256;
        br[i] = idx >> 3; bc[i] = (idx & 7) << 2;
        bptr[i] = Bw + (size_t)(n0 + br[i]) * K + bc[i];
    }

    float acc[2][4][4];
    #pragma unroll
    for (int mt = 0; mt < 2; mt++)
        #pragma unroll
        for (int nt = 0; nt < 4; nt++)
            #pragma unroll
            for (int e = 0; e < 4; e++) acc[mt][nt][e] = 0.f;

    uint4 pa[2];
    float4 pb[2];
    #pragma unroll
    for (int i = 0; i < 2; i++) pa[i] = *(const uint4*)(aptr[i]);
    #pragma unroll
    for (int i = 0; i < 2; i++) pb[i] = *(const float4*)(bptr[i]);

    #pragma unroll
    for (int i = 0; i < 2; i++) {
        uint4 raw = pa[i];
        if (op == 2) {
            float2 v[4];
            uint32_t* rw = (uint32_t*)&raw;
            #pragma unroll
            for (int wd = 0; wd < 4; wd++) v[wd] = __half22float2(*(__half2*)&rw[wd]);
            const float* wtp = (const float*)&wt4[i];
            #pragma unroll
            for (int j = 0; j < 4; j++) {
                uint4 nr = *(const uint4*)(nph[i][j]);
                uint32_t* nw = (uint32_t*)&nr;
                #pragma unroll
                for (int wd = 0; wd < 4; wd++) {
                    float2 nv = __half22float2(*(__half2*)&nw[wd]);
                    v[wd].x += wtp[j]*nv.x; v[wd].y += wtp[j]*nv.y;
                }
            }
            #pragma unroll
            for (int wd = 0; wd < 4; wd++) rw[wd] = f22h2(v[wd].x, v[wd].y);
        }
        *(uint4*)(As + ar[i]*KP + (ac[i] >> 1)) = raw;
    }
    #pragma unroll
    for (int i = 0; i < 2; i++) *(uint2*)(Bs + br[i]*KP + (bc[i] >> 1)) = cvt4h(pb[i]);
    __syncthreads();

    int nkt = K >> 5;
    for (int kt = 0; kt < nkt; kt++) {
        int buf = kt & 1;
        int off = (kt + 1) << 5;
        if (kt + 1 < nkt) {
            #pragma unroll
            for (int i = 0; i < 2; i++) pa[i] = *(const uint4*)(aptr[i] + off);
            #pragma unroll
            for (int i = 0; i < 2; i++) pb[i] = *(const float4*)(bptr[i] + off);
        }
        uint32_t sbA = sbase + (buf*AS_SZ)*4;
        uint32_t sbB = sbase + (2*AS_SZ + buf*BS_SZ)*4;
        #pragma unroll
        for (int ks = 0; ks < 2; ks++) {
            int k0 = ks*8;
            uint32_t af[2][4], bf[2][4];
            ldsm_x4(af[0], sbA + ((wm*32 +      la_row)*KP + k0 + la_kw)*4);
            ldsm_x4(af[1], sbA + ((wm*32 + 16 + la_row)*KP + k0 + la_kw)*4);
            ldsm_x4(bf[0], sbB + ((wn*32 +      lb_row)*KP + k0 + lb_kw)*4);
            ldsm_x4(bf[1], sbB + ((wn*32 + 16 + lb_row)*KP + k0 + lb_kw)*4);
            #pragma unroll
            for (int nt = 0; nt < 4; nt++) {
                uint32_t b0 = bf[nt>>1][(nt&1)*2], b1 = bf[nt>>1][(nt&1)*2+1];
                mma_f16(acc[0][nt], af[0], b0, b1);
                mma_f16(acc[1][nt], af[1], b0, b1);
            }
        }
        if (kt + 1 < nkt) {
            uint32_t* Asn = As + (buf^1)*AS_SZ;
            uint32_t* Bsn = Bs + (buf^1)*BS_SZ;
            #pragma unroll
            for (int i = 0; i < 2; i++) {
                uint4 raw = pa[i];
                if (op == 2) {
                    float2 v[4];
                    uint32_t* rw = (uint32_t*)&raw;
                    #pragma unroll
                    for (int wd = 0; wd < 4; wd++) v[wd] = __half22float2(*(__half2*)&rw[wd]);
                    const float* wtp = (const float*)&wt4[i];
                    #pragma unroll
                    for (int j = 0; j < 4; j++) {
                        uint4 nr = *(const uint4*)(nph[i][j] + off);
                        uint32_t* nw = (uint32_t*)&nr;
                        #pragma unroll
                        for (int wd = 0; wd < 4; wd++) {
                            float2 nv = __half22float2(*(__half2*)&nw[wd]);
                            v[wd].x += wtp[j]*nv.x; v[wd].y += wtp[j]*nv.y;
                        }
                    }
                    #pragma unroll
                    for (int wd = 0; wd < 4; wd++) rw[wd] = f22h2(v[wd].x, v[wd].y);
                }
                *(uint4*)(Asn + ar[i]*KP + (ac[i] >> 1)) = raw;
            }
            #pragma unroll
            for (int i = 0; i < 2; i++) *(uint2*)(Bsn + br[i]*KP + (bc[i] >> 1)) = cvt4h(pb[i]);
        }
        __syncthreads();
    }

    if (op == 0) {
        __half* Ob = g_vth + (size_t)b * NN * CC;
        __half* V1 = g_v1th + (size_t)b * CC * NKEEP;
        int pos[2][2];
        #pragma unroll
        for (int mt = 0; mt < 2; mt++) {
            pos[mt][0] = g_pos[b*NN + m0 + wm*32 + mt*16 + g];
            pos[mt][1] = g_pos[b*NN + m0 + wm*32 + mt*16 + g + 8];
        }
        #pragma unroll
        for (int nt = 0; nt < 4; nt++) {
            int ncol = n0 + wn*32 + nt*8 + 2*t4;
            float b0v = bias[ncol];
            float b1v = bias[ncol + 1];
            #pragma unroll
            for (int mt = 0; mt < 2; mt++) {
                int row0 = m0 + wm*32 + mt*16 + g;
                float2 o0 = make_float2(acc[mt][nt][0] + b0v, acc[mt][nt][1] + b1v);
                float2 o1 = make_float2(acc[mt][nt][2] + b0v, acc[mt][nt][3] + b1v);
                uint32_t h0 = f22h2(o0.x, o0.y);
                uint32_t h1 = f22h2(o1.x, o1.y);
                *(uint32_t*)&Ob[(size_t)row0 * CC + ncol]     = h0;
                *(uint32_t*)&Ob[(size_t)(row0+8) * CC + ncol] = h1;
                if (pos[mt][0] >= 0) {
                    V1[(size_t)ncol*NKEEP + pos[mt][0]]     = __float2half_rn(o0.x);
                    V1[(size_t)(ncol+1)*NKEEP + pos[mt][0]] = __float2half_rn(o0.y);
                }
                if (pos[mt][1] >= 0) {
                    V1[(size_t)ncol*NKEEP + pos[mt][1]]     = __float2half_rn(o1.x);
                    V1[(size_t)(ncol+1)*NKEEP + pos[mt][1]] = __float2half_rn(o1.y);
                }
            }
        }
    } else {
        __half* Obh = ((op == 1) ? g_q1h : g_k1h) + (size_t)b * NKEEP * CC;
        #pragma unroll
        for (int nt = 0; nt < 4; nt++) {
            int ncol = n0 + wn*32 + nt*8 + 2*t4;
            float b0v = bias[ncol];
            float b1v = bias[ncol + 1];
            #pragma unroll
            for (int mt = 0; mt < 2; mt++) {
                int row0 = m0 + wm*32 + mt*16 + g;
                *(uint32_t*)&Obh[(size_t)row0 * CC + ncol] =
                    f22h2((acc[mt][nt][0] + b0v) * scale, (acc[mt][nt][1] + b1v) * scale);
                *(uint32_t*)&Obh[(size_t)(row0+8) * CC + ncol] =
                    f22h2((acc[mt][nt][2] + b0v) * scale, (acc[mt][nt][3] + b1v) * scale);
            }
        }
    }
}

// ================= final out GEMM (A fp16, transposed epilogue) =================
__global__ void __launch_bounds__(256, 2) k_gemmO(
    const float* __restrict__ Bm,
    const float* __restrict__ bias,
    float* __restrict__ Out)
{
    const int K = CC;
    extern __shared__ uint32_t sm[];
    uint32_t* As = sm;
    uint32_t* Bs = sm + 2*AS_SZ;
    uint32_t sbase = (uint32_t)__cvta_generic_to_shared(sm);
    int tid = threadIdx.x;
    int lane = tid & 31, wid = tid >> 5;
    int wm = wid & 3, wn = wid >> 2;
    int g = lane >> 2, t4 = lane & 3;
    int la_row = lane & 15, la_kw = (lane >> 4) << 2;
    int lb_row = ((lane >> 4) & 1) * 8 + (lane & 7), lb_kw = ((lane >> 3) & 1) << 2;
    int b = blockIdx.z;
    int m0 = blockIdx.x * 128, n0 = blockIdx.y * 64;

    const __half* Abh = g_out2Th + (size_t)b * NN * CC;

    const __half* aptr[2];
    int ar[2], ac[2];
    #pragma unroll
    for (int i = 0; i < 2; i++) {
        int idx = tid + i*256;
        ar[i] = idx >> 2; ac[i] = (idx & 3) << 3;
        aptr[i] = Abh + (size_t)(m0 + ar[i]) * K + ac[i];
    }
    const float* bptr[2];
    int br[2], bc[2];
    #pragma unroll
    for (int i = 0; i < 2; i++) {
        int idx = tid + i*256;
        br[i] = idx >> 3; bc[i] = (idx & 7) << 2;
        bptr[i] = Bm + (size_t)(n0 + br[i]) * K + bc[i];
    }

    float acc[2][4][4];
    #pragma unroll
    for (int mt = 0; mt < 2; mt++)
        #pragma unroll
        for (int nt = 0; nt < 4; nt++)
            #pragma unroll
            for (int e = 0; e < 4; e++) acc[mt][nt][e] = 0.f;

    uint4 pa[2];
    float4 pb[2];
    #pragma unroll
    for (int i = 0; i < 2; i++) pa[i] = *(const uint4*)(aptr[i]);
    #pragma unroll
    for (int i = 0; i < 2; i++) pb[i] = *(const float4*)(bptr[i]);
    #pragma unroll
    for (int i = 0; i < 2; i++) *(uint4*)(As + ar[i]*KP + (ac[i] >> 1)) = pa[i];
    #pragma unroll
    for (int i = 0; i < 2; i++) *(uint2*)(Bs + br[i]*KP + (bc[i] >> 1)) = cvt4h(pb[i]);
    __syncthreads();

    int nkt = K >> 5;
    for (int kt = 0; kt < nkt; kt++) {
        int buf = kt & 1;
        int off = (kt + 1) << 5;
        if (kt + 1 < nkt) {
            #pragma unroll
            for (int i = 0; i < 2; i++) pa[i] = *(const uint4*)(aptr[i] + off);
            #pragma unroll
            for (int i = 0; i < 2; i++) pb[i] = *(const float4*)(bptr[i] + off);
        }
        uint32_t sbA = sbase + (buf*AS_SZ)*4;
        uint32_t sbB = sbase + (2*AS_SZ + buf*BS_SZ)*4;
        #pragma unroll
        for (int ks = 0; ks < 2; ks++) {
            int k0 = ks*8;
            uint32_t af[2][4], bf[2][4];
            ldsm_x4(af[0], sbA + ((wm*32 +      la_row)*KP + k0 + la_kw)*4);
            ldsm_x4(af[1], sbA + ((wm*32 + 16 + la_row)*KP + k0 + la_kw)*4);
            ldsm_x4(bf[0], sbB + ((wn*32 +      lb_row)*KP + k0 + lb_kw)*4);
            ldsm_x4(bf[1], sbB + ((wn*32 + 16 + lb_row)*KP + k0 + lb_kw)*4);
            #pragma unroll
            for (int nt = 0; nt < 4; nt++) {
                uint32_t b0 = bf[nt>>1][(nt&1)*2], b1 = bf[nt>>1][(nt&1)*2+1];
                mma_f16(acc[0][nt], af[0], b0, b1);
                mma_f16(acc[1][nt], af[1], b0, b1);
            }
        }
        if (kt + 1 < nkt) {
            uint32_t* Asn = As + (buf^1)*AS_SZ;
            uint32_t* Bsn = Bs + (buf^1)*BS_SZ;
            #pragma unroll
            for (int i = 0; i < 2; i++) *(uint4*)(Asn + ar[i]*KP + (ac[i] >> 1)) = pa[i];
            #pragma unroll
            for (int i = 0; i < 2; i++) *(uint2*)(Bsn + br[i]*KP + (bc[i] >> 1)) = cvt4h(pb[i]);
        }
        __syncthreads();
    }

    float* st = (float*)sm;
    __syncthreads();
    #pragma unroll
    for (int nt = 0; nt < 4; nt++) {
        int nl = wn*32 + nt*8 + 2*t4;
        float b0v = bias[n0 + nl];
        float b1v = bias[n0 + nl + 1];
        #pragma unroll
        for (int mt = 0; mt < 2; mt++) {
            int ml = wm*32 + mt*16 + g;
            st[nl*132 + ml]         = acc[mt][nt][0] + b0v;
            st[(nl+1)*132 + ml]     = acc[mt][nt][1] + b1v;
            st[nl*132 + ml + 8]     = acc[mt][nt][2] + b0v;
            st[(nl+1)*132 + ml + 8] = acc[mt][nt][3] + b1v;
        }
    }
    __syncthreads();
    for (int l = tid; l < 64*32; l += 256) {
        int r = l >> 5, c4v = (l & 31) << 2;
        float4 v = *(float4*)&st[r*132 + c4v];
        *(float4*)&Out[((size_t)b*CC + n0 + r)*NN + m0 + c4v] = v;
    }
}

// ================= flash attention: 64 keys/iter (R13 validated, reverted) =======
#define F_QS 0
#define F_KS 12800
#define F_VS 25600
#define F_PS 39424
#define F_SC 44032
#define F_LB 44160
#define F_TOT 44288
#define NTILES (NKEEP/64)

__global__ void __launch_bounds__(256, 1) k_flash() {
    extern __shared__ uint32_t sm[];
    uint32_t* Qs = sm + F_QS;
    uint32_t* Ps = sm + F_PS;
    float* scaleb = (float*)(sm + F_SC);
    float* lb = (float*)(sm + F_LB);
    uint32_t sbase = (uint32_t)__cvta_generic_to_shared(sm);

    int tid = threadIdx.x, lane = tid & 31, w = tid >> 5;
    int g = lane >> 2, t4 = lane & 3;
    int la_row = lane & 15, la_kw = (lane >> 4) << 2;
    int lb_row = ((lane >> 4) & 1) * 8 + (lane & 7), lb_kw = ((lane >> 3) & 1) << 2;
    int b = blockIdx.y, m0 = blockIdx.x * 128;

    const __half* Qg = g_q1h + ((size_t)b*NKEEP + m0)*CC;
    const __half* Kg = g_k1h + (size_t)b*NKEEP*CC;
    const __half* Vg = g_v1th + (size_t)b*CC*NKEEP;

    #pragma unroll
    for (int j = 0; j < 12; j++) {
        int idx = tid + j*256;
        int r = idx/24, ch = idx%24;
        *(uint4*)&Qs[r*100 + ch*4] = *(const uint4*)(Qg + (size_t)r*CC + ch*8);
    }

    int rK[6], cKc[6], rV[6], cVc[6];
    #pragma unroll
    for (int j = 0; j < 6; j++) {
        int idx = tid + j*256;
        rK[j] = idx/24; cKc[j] = idx%24;
        rV[j] = idx/8;  cVc[j] = idx%8;
    }
    #pragma unroll
    for (int j = 0; j < 6; j++) {
        CP_ASYNC16(sbase + (F_KS + rK[j]*100 + cKc[j]*4)*4,
                   Kg + (size_t)rK[j]*CC + cKc[j]*8);
        CP_ASYNC16(sbase + (F_VS + rV[j]*36 + cVc[j]*4)*4,
                   Vg + (size_t)rV[j]*NKEEP + cVc[j]*8);
    }
    CP_COMMIT();
    CP_WAIT0();
    __syncthreads();

    int wm = w >> 1, wn = w & 1;
    float oat[3][8][4];
    #pragma unroll
    for (int mt = 0; mt < 3; mt++)
        #pragma unroll
        for (int nt = 0; nt < 8; nt++)
            #pragma unroll
            for (int e = 0; e < 4; e++) oat[mt][nt][e] = 0.f;
    float m_r0 = -1e30f, m_r1 = -1e30f, l_r0 = 0.f, l_r1 = 0.f;

    int qr0 = w * 16;
    #pragma unroll 1
    for (int kt = 0; kt < NTILES; kt++) {
        int buf = kt & 1;
        if (kt + 1 < NTILES) {
            int k0n = (kt + 1) * 64;
            #pragma unroll
            for (int j = 0; j < 6; j++) {
                CP_ASYNC16(sbase + (F_KS + (buf^1)*6400 + rK[j]*100 + cKc[j]*4)*4,
                           Kg + (size_t)(k0n + rK[j])*CC + cKc[j]*8);
                CP_ASYNC16(sbase + (F_VS + (buf^1)*6912 + rV[j]*36 + cVc[j]*4)*4,
                           Vg + (size_t)rV[j]*NKEEP + k0n + cVc[j]*8);
            }
            CP_COMMIT();
        }
        float sacc[8][4];
        #pragma unroll
        for (int nt = 0; nt < 8; nt++)
            #pragma unroll
            for (int e = 0; e < 4; e++) sacc[nt][e] = 0.f;
        #pragma unroll
        for (int ks = 0; ks < 12; ks++) {
            int k0 = ks*8;
            uint32_t a[4];
            ldsm_x4(a, sbase + (F_QS + (qr0 + la_row)*100 + k0 + la_kw)*4);
            #pragma unroll
            for (int nb = 0; nb < 4; nb++) {
                uint32_t bf[4];
                ldsm_x4(bf, sbase + (F_KS + buf*6400 + (nb*16 + lb_row)*100 + k0 + lb_kw)*4);
                mma_f16(sacc[2*nb],   a, bf[0], bf[1]);
                mma_f16(sacc[2*nb+1], a, bf[2], bf[3]);
            }
        }
        float mx0 = -1e30f, mx1 = -1e30f;
        #pragma unroll
        for (int nt = 0; nt < 8; nt++) {
            mx0 = fmaxf(mx0, fmaxf(sacc[nt][0], sacc[nt][1]));
            mx1 = fmaxf(mx1, fmaxf(sacc[nt][2], sacc[nt][3]));
        }
        mx0 = fmaxf(mx0, __shfl_xor_sync(~0u, mx0, 1));
        mx0 = fmaxf(mx0, __shfl_xor_sync(~0u, mx0, 2));
        mx1 = fmaxf(mx1, __shfl_xor_sync(~0u, mx1, 1));
        mx1 = fmaxf(mx1, __shfl_xor_sync(~0u, mx1, 2));
        float mn0 = fmaxf(m_r0, mx0), mn1 = fmaxf(m_r1, mx1);
        float al0 = __expf(m_r0 - mn0), al1 = __expf(m_r1 - mn1);
        float s0 = 0.f, s1 = 0.f;
        #pragma unroll
        for (int nt = 0; nt < 8; nt++) {
            float e00 = __expf(sacc[nt][0] - mn0);
            float e01 = __expf(sacc[nt][1] - mn0);
            float e10 = __expf(sacc[nt][2] - mn1);
            float e11 = __expf(sacc[nt][3] - mn1);
            s0 += e00 + e01; s1 += e10 + e11;
            Ps[(qr0+g)*36   + nt*4 + t4] = f22h2(e00, e01);
            Ps[(qr0+g+8)*36 + nt*4 + t4] = f22h2(e10, e11);
        }
        s0 += __shfl_xor_sync(~0u, s0, 1); s0 += __shfl_xor_sync(~0u, s0, 2);
        s1 += __shfl_xor_sync(~0u, s1, 1); s1 += __shfl_xor_sync(~0u, s1, 2);
        l_r0 = l_r0 * al0 + s0;
        l_r1 = l_r1 * al1 + s1;
        m_r0 = mn0; m_r1 = mn1;
        if (t4 == 0) {
            scaleb[qr0+g]   = al0;
            scaleb[qr0+g+8] = al1;
            if (kt == NTILES-1) { lb[qr0+g] = l_r0; lb[qr0+g+8] = l_r1; }
        }
        __syncthreads();
        #pragma unroll
        for (int nt = 0; nt < 8; nt++) {
            int qc = wn*64 + nt*8 + 2*t4;
            float a0 = scaleb[qc], a1 = scaleb[qc+1];
            #pragma unroll
            for (int mt = 0; mt < 3; mt++) {
                oat[mt][nt][0] *= a0; oat[mt][nt][1] *= a1;
                oat[mt][nt][2] *= a0; oat[mt][nt][3] *= a1;
            }
        }
        #pragma unroll
        for (int ks = 0; ks < 4; ks++) {
            int k0 = ks*8;
            uint32_t pf[4][4];
            #pragma unroll
            for (int ntp = 0; ntp < 4; ntp++)
                ldsm_x4(pf[ntp], sbase + (F_PS + (wn*64 + ntp*16 + lb_row)*36 + k0 + lb_kw)*4);
            #pragma unroll
            for (int mt = 0; mt < 3; mt++) {
                int cr = wm*48 + mt*16;
                uint32_t a[4];
                ldsm_x4(a, sbase + (F_VS + buf*6912 + (cr + la_row)*36 + k0 + la_kw)*4);
                #pragma unroll
                for (int nt = 0; nt < 8; nt++)
                    mma_f16(oat[mt][nt], a, pf[nt>>1][(nt&1)*2], pf[nt>>1][(nt&1)*2+1]);
            }
        }
        CP_WAIT0();
        __syncthreads();
    }

    float* Ot = (float*)sm;
    #pragma unroll
    for (int nt = 0; nt < 8; nt++) {
        int qc = wn*64 + nt*8 + 2*t4;
        float li0 = 1.f / lb[qc], li1 = 1.f / lb[qc+1];
        #pragma unroll
        for (int mt = 0; mt < 3; mt++) {
            int cr = wm*48 + mt*16;
            Ot[qc*196 + cr+g]       = oat[mt][nt][0] * li0;
            Ot[(qc+1)*196 + cr+g]   = oat[mt][nt][1] * li1;
            Ot[qc*196 + cr+g+8]     = oat[mt][nt][2] * li0;
            Ot[(qc+1)*196 + cr+g+8] = oat[mt][nt][3] * li1;
        }
    }
    __syncthreads();
    #pragma unroll
    for (int j = 0; j < 24; j++) {
        int idx = tid + j*256;
        int r = idx/48, c4v = (idx%48)*4;
        int tok = g_keep[b*NKEEP + m0 + r];
        float4 v = *(float4*)&Ot[r*196 + c4v];
        uint2 h = cvt4h(v);
        *(uint2*)&g_otokTh[((size_t)b*NN + tok)*CC + c4v] = h;
    }
}

// ================= front end (+ fused fp16 x transpose) =================
__global__ void k_front(const float* __restrict__ x,
    const float* __restrict__ in_w, const float* __restrict__ in_b,
    const float* __restrict__ ln_w, const float* __restrict__ ln_b,
    const float* __restrict__ ow1, const float* __restrict__ ob1,
    const float* __restrict__ ow2, const float* __restrict__ ob2,
    const float* __restrict__ mw1, const float* __restrict__ mb1,
    const float* __restrict__ mw2, const float* __restrict__ mb2)
{
    __shared__ float cond[CD][33];
    __shared__ float fb[C4][33];
    __shared__ float mu_s[32], rs_s[32];
    __shared__ float hb[C8][33];
    int b = blockIdx.y;
    int n0 = blockIdx.x * 32;
    int tid = threadIdx.x;

    for (int l = tid; l < CC*32; l += 256) {
        int c = l >> 5, px = l & 31;
        cond[c][px] = x[((b*CC + c) << 12) + n0 + px];
    }
    if (tid < 32) {
        int n = n0 + tid;
        int h = n >> 6, w = n & 63;
        cond[192][tid] = -1.0f + 2.0f * (float)w / 63.0f;
        cond[193][tid] = -1.0f + 2.0f * (float)h / 63.0f;
    }
    __syncthreads();

    for (int l = tid; l < 32*96; l += 256) {
        int px = l / 96, c2 = (l % 96) * 2;
        *(uint32_t*)&g_xth[((size_t)b*NN + n0 + px)*CC + c2] =
            f22h2(cond[c2][px], cond[c2+1][px]);
    }

    int px = tid & 31;
    for (int pass = 0; pass < 6; pass++) {
        int c = pass*8 + (tid >> 5);
        float acc = in_b[c];
        const float* wr = in_w + c*CD;
        #pragma unroll 2
        for (int k = 0; k < CD; k++) acc += wr[k] * cond[k][px];
        fb[c][px] = acc;
    }
    __syncthreads();

    if (tid < 32) {
        float s = 0.f, s2 = 0.f;
        for (int c = 0; c < C4; c++) { float v = fb[c][tid]; s += v; s2 += v*v; }
        float mu = s / (float)C4;
        float var = s2 / (float)C4 - mu*mu;
        mu_s[tid] = mu;
        rs_s[tid] = rsqrtf(var + 1e-6f);
    }
    __syncthreads();

    for (int l = tid; l < C4*32; l += 256) {
        int c = l >> 5, p = l & 31;
        float v = (fb[c][p] - mu_s[p]) * rs_s[p] * ln_w[c] + ln_b[c];
        v = v > 0.f ? v : 0.1f*v;
        fb[c][p] = v;
        g_f[(b*C4 + c)*NN + n0 + p] = v;
    }
    __syncthreads();

    for (int l = tid; l < C8*32; l += 256) {
        int j = l >> 5, p = l & 31;
        float acc = ob1[j];
        const float* wr = ow1 + j*C4;
        #pragma unroll 4
        for (int c = 0; c < C4; c++) acc += wr[c] * fb[c][p];
        hb[j][p] = acc > 0.f ? acc : 0.1f*acc;
    }
    __syncthreads();

    if (tid < 64) {
        int d = tid >> 5, p = tid & 31;
        float acc = ob2[d];
        const float* wr = ow2 + d*C8;
        #pragma unroll
        for (int j = 0; j < C8; j++) acc += wr[j] * hb[j][p];
        g_off[(b*2 + d)*NN + n0 + p] = tanhf(acc) * 8.0f;
    }
    if (tid >= 64 && tid < 96) {
        int p = tid - 64;
        float s = 0.f;
        for (int c = 0; c < C4; c++) s += fb[c][p];
        float t = s / (float)C4;
        float s1 = t * mw1[0] + mb1[0];
        s1 = s1 > 0.f ? s1 : 0.1f*s1;
        float l0 = s1 * mw2[0] + mb2[0];
        float l1 = s1 * mw2[1] + mb2[1];
        g_score[b*NN + n0 + p] = 1.0f / (1.0f + expf(l1 - l0));
    }
}

// ================= merged aux: sa (blocks 0-3, 2ch/round) | stats+ca+topk (block 4)
__device__ __forceinline__ unsigned int ford(float f) {
    unsigned int u = __float_as_uint(f);
    return (u & 0x80000000u) ? ~u : (u | 0x80000000u);
}
__global__ void __launch_bounds__(1024) k_aux(
    const float* __restrict__ caw, const float* __restrict__ cab,
    const float* __restrict__ saw, const float* __restrict__ sab)
{
    extern __shared__ char smaux[];
    int b = blockIdx.y;
    int tid = threadIdx.x;
    int lane = tid & 31, wid = tid >> 5;

    if (blockIdx.x < 4) {
        // ---------- sa: 16 rows per block, 2 channels per smem round ----------
        float* wsh = (float*)smaux;              // C4*9
        float* smf = wsh + C4*9;                 // [2][18][64]
        int h0 = blockIdx.x * 16;
        for (int l = tid; l < C4*9; l += 1024) wsh[l] = saw[l];
        int lw = tid & 63, lh = tid >> 6;
        float acc = sab[0];
        const float* fb = g_f + b*C4*NN;
        for (int c = 0; c < C4; c += 2) {
            __syncthreads();
            for (int l = tid; l < 2*18*64; l += 1024) {
                int cc = l / (18*64);
                int rem = l % (18*64);
                int r = rem >> 6, ww = rem & 63;
                int hh = h0 - 1 + r;
                smf[l] = (hh >= 0 && hh < HH) ? fb[(c+cc)*NN + hh*64 + ww] : 0.f;
            }
            __syncthreads();
            #pragma unroll
            for (int cc = 0; cc < 2; cc++) {
                const float* strip = smf + cc*18*64;
                #pragma unroll
                for (int dh = 0; dh < 3; dh++) {
                    float w0 = wsh[(c+cc)*9+dh*3+0], w1 = wsh[(c+cc)*9+dh*3+1], w2 = wsh[(c+cc)*9+dh*3+2];
                    const float* row = strip + (lh + dh)*64;
                    float vm = (lw > 0)  ? row[lw-1] : 0.f;
                    float vc = row[lw];
                    float vp = (lw < 63) ? row[lw+1] : 0.f;
                    acc += w0*vm + w1*vc + w2*vp;
                }
            }
        }
        g_sa[b*NN + (h0+lh)*64 + lw] = 1.f/(1.f + __expf(-acc));
        return;
    }

    ull* keys  = (ull*)smaux;
    int* hist  = (int*)(smaux + 32768);
    int* scan_ = (int*)(smaux + 33792);
    ull* selp  = (ull*)(smaux + 34816);
    int* selk  = (int*)(smaux + 34824);
    int* wsum  = (int*)(smaux + 34832);
    float* fm  = (float*)(smaux + 34960);

    for (int c = wid; c < C4; c += 32) {
        const float* p = g_f + (b*C4 + c)*NN;
        float s = 0.f;
        for (int i = lane; i < NN; i += 32) s += p[i];
        #pragma unroll
        for (int o = 16; o; o >>= 1) s += __shfl_xor_sync(~0u, s, o);
        if (lane == 0) fm[c] = s / (float)NN;
    }
    __syncthreads();
    if (tid < CC) {
        float acc = cab[tid];
        #pragma unroll 4
        for (int c = 0; c < C4; c++) acc += caw[tid*C4 + c] * fm[c];
        g_ca[b*CC + tid] = 1.0f / (1.0f + __expf(-acc));
    }

    for (int l = tid; l < NN; l += 1024) {
        unsigned int o = ford(g_score[b*NN + l]) ^ 0xFFFFFFFFu;
        keys[l] = ((ull)o << 32) | (unsigned int)l;
    }
    if (tid == 0) { selp[0] = 0; selk[0] = NKEEP - 1; }
    __syncthreads();

    const int bseq[6] = {7, 6, 5, 4, 1, 0};
    ull prefix = 0, mask = 0;
    #pragma unroll 1
    for (int bi = 0; bi < 6; bi++) {
        int sh = bseq[bi] * 8;
        if (tid < 256) hist[tid] = 0;
        __syncthreads();
        for (int l = tid; l < NN; l += 1024) {
            ull k = keys[l];
            if ((k & mask) == prefix) atomicAdd(&hist[(int)((k >> sh) & 0xFF)], 1);
        }
        __syncthreads();
        if (tid < 256) scan_[tid] = hist[tid];
        __syncthreads();
        #pragma unroll
        for (int off = 1; off < 256; off <<= 1) {
            int v = 0;
            if (tid < 256 && tid >= off) v = scan_[tid - off];
            __syncthreads();
            if (tid < 256) scan_[tid] += v;
            __syncthreads();
        }
        int kcur = selk[0];
        __syncthreads();
        if (tid < 256) {
            int incl = scan_[tid], excl = incl - hist[tid];
            if (kcur >= excl && kcur < incl) {
                selp[0] = prefix | ((ull)tid << sh);
                selk[0] = kcur - excl;
            }
        }
        __syncthreads();
        prefix = selp[0];
        mask |= (0xFFull << sh);
        __syncthreads();
    }
    ull kstar = prefix;

    int base = tid * 4;
    int kept[4], c = 0;
    #pragma unroll
    for (int j = 0; j < 4; j++) {
        kept[j] = (keys[base + j] <= kstar) ? 1 : 0;
        c += kept[j];
    }
    int incl = c;
    #pragma unroll
    for (int o = 1; o < 32; o <<= 1) {
        int v = __shfl_up_sync(~0u, incl, o);
        if (lane >= o) incl += v;
    }
    if (lane == 31) wsum[wid] = incl;
    __syncthreads();
    if (wid == 0) {
        int v = (lane < 32) ? wsum[lane] : 0;
        #pragma unroll
        for (int o = 1; o < 32; o <<= 1) {
            int u = __shfl_up_sync(~0u, v, o);
            if (lane >= o) v += u;
        }
        wsum[lane] = v;
    }
    __syncthreads();
    int offset = (wid > 0 ? wsum[wid - 1] : 0) + incl - c;
    #pragma unroll
    for (int j = 0; j < 4; j++) {
        int tok = base + j;
        if (kept[j]) {
            g_keep[b*NKEEP + offset] = tok;
            g_pos[b*NN + tok] = offset;
            offset++;
        } else {
            g_pos[b*NN + tok] = -1;
        }
    }
}

// ================= token-major depthwise 3x3 + gelu*ca + residual (fp16 in/out) ====
__global__ void __launch_bounds__(192) k_dwT(const float* __restrict__ csw, const float* __restrict__ csb) {
    extern __shared__ float sdw[];
    float* tile = sdw;
    float* wsm = sdw + 100*192;
    int b = blockIdx.y;
    int t = blockIdx.x;
    int th0 = (t >> 3) * 8, tw0 = (t & 7) * 8;
    int tid = threadIdx.x;
    for (int l = tid; l < 192*9; l += 192) wsm[l] = csw[l];
    const __half* inb = g_otokTh + (size_t)b*NN*CC;
    const __half* vtb = g_vth + (size_t)b*NN*CC;
    for (int l = tid; l < 100*48; l += 192) {
        int pos = l / 48, c4v = (l % 48)*4;
        int hh = th0 - 1 + pos/10, ww = tw0 - 1 + pos%10;
        float4 v = make_float4(0.f, 0.f, 0.f, 0.f);
        if (hh >= 0 && hh < 64 && ww >= 0 && ww < 64) {
            int n = hh*64 + ww;
            uint2 raw;
            if (g_pos[b*NN + n] >= 0) {
                raw = *(const uint2*)(inb + (size_t)n*CC + c4v);
                float2 lo = __half22float2(*(__half2*)&raw.x);
                float2 hi = __half22float2(*(__half2*)&raw.y);
                v = make_float4(lo.x, lo.y, hi.x, hi.y);
            } else {
                raw = *(const uint2*)(vtb + (size_t)n*CC + c4v);
                float2 lo = __half22float2(*(__half2*)&raw.x);
                float2 hi = __half22float2(*(__half2*)&raw.y);
                float s = g_sa[b*NN + n];
                v = make_float4(lo.x*s, lo.y*s, hi.x*s, hi.y*s);
            }
        }
        *(float4*)&tile[pos*192 + c4v] = v;
    }
    __syncthreads();

    int c4 = (tid % 48) * 4;
    int pxb = tid / 48;
    float wreg[9][4];
    #pragma unroll
    for (int tap = 0; tap < 9; tap++)
        #pragma unroll
        for (int e = 0; e < 4; e++)
            wreg[tap][e] = wsm[(c4+e)*9 + tap];
    float bv[4], cav[4];
    #pragma unroll
    for (int e = 0; e < 4; e++) { bv[e] = csb[c4+e]; cav[e] = g_ca[b*CC + c4 + e]; }

    __half* outb = g_out2Th + (size_t)b*NN*CC;
    for (int j = 0; j < 16; j++) {
        int px = pxb*16 + j;
        int lh = px >> 3, lw2 = px & 7;
        float acc[4] = {bv[0], bv[1], bv[2], bv[3]};
        #pragma unroll
        for (int dh = 0; dh < 3; dh++)
            #pragma unroll
            for (int dw_ = 0; dw_ < 3; dw_++) {
                int pos = (lh+dh)*10 + (lw2+dw_);
                float4 v = *(const float4*)&tile[pos*192 + c4];
                int tap = dh*3 + dw_;
                acc[0] += wreg[tap][0]*v.x; acc[1] += wreg[tap][1]*v.y;
                acc[2] += wreg[tap][2]*v.z; acc[3] += wreg[tap][3]*v.w;
            }
        float4 cen = *(const float4*)&tile[((lh+1)*10 + (lw2+1))*192 + c4];
        float* cenp = (float*)&cen;
        float o[4];
        #pragma unroll
        for (int e = 0; e < 4; e++) {
            float a = acc[e];
            float x3 = a*a*a;
            float gg = 0.5f*a*(1.0f + tanhf(0.7978845608028654f*(a + 0.044715f*x3)));
            o[e] = gg * cav[e] + cenp[e];
        }
        int n = (th0+lh)*64 + (tw0+lw2);
        uint2 o2 = make_uint2(f22h2(o[0], o[1]), f22h2(o[2], o[3]));
        *(uint2*)(outb + (size_t)n*CC + c4) = o2;
    }
}

// ================= host =================
extern "C" void kernel_launch(void* const* d_in, const int* in_sizes, int n_in,
                              void* d_out, int out_size) {
    const float* x     = (const float*)d_in[0];
    const float* in_w  = (const float*)d_in[1];
    const float* in_b  = (const float*)d_in[2];
    const float* ln_w  = (const float*)d_in[3];
    const float* ln_b  = (const float*)d_in[4];
    const float* ow1   = (const float*)d_in[5];
    const float* ob1   = (const float*)d_in[6];
    const float* ow2   = (const float*)d_in[7];
    const float* ob2   = (const float*)d_in[8];
    const float* caw   = (const float*)d_in[9];
    const float* cab   = (const float*)d_in[10];
    const float* saw   = (const float*)d_in[11];
    const float* sab   = (const float*)d_in[12];
    const float* mw1   = (const float*)d_in[13];
    const float* mb1   = (const float*)d_in[14];
    const float* mw2   = (const float*)d_in[15];
    const float* mb2   = (const float*)d_in[16];
    const float* v_w   = (const float*)d_in[17];
    const float* v_b   = (const float*)d_in[18];
    const float* q_w   = (const float*)d_in[19];
    const float* q_b   = (const float*)d_in[20];
    const float* k_w   = (const float*)d_in[21];
    const float* k_b   = (const float*)d_in[22];
    const float* cs_w  = (const float*)d_in[23];
    const float* cs_b  = (const float*)d_in[24];
    const float* out_w = (const float*)d_in[25];
    const float* out_b = (const float*)d_in[26];
    float* out = (float*)d_out;

    const int SMEM_G = 8448 * 4;
    cudaFuncSetAttribute(k_gemm3, cudaFuncAttributeMaxDynamicSharedMemorySize, SMEM_G);
    cudaFuncSetAttribute(k_gemmO, cudaFuncAttributeMaxDynamicSharedMemorySize, SMEM_G);
    const int SMEM_F = F_TOT * 4;  // 177152
    cudaFuncSetAttribute(k_flash, cudaFuncAttributeMaxDynamicSharedMemorySize, SMEM_F);
    const int SMEM_DW = (100*192 + 192*9) * 4;
    cudaFuncSetAttribute(k_dwT, cudaFuncAttributeMaxDynamicSharedMemorySize, SMEM_DW);
    const int SMEM_AUX = 35200;   // covers sa path (C4*9*4 + 2*18*64*4 = 10944) and topk path
    cudaFuncSetAttribute(k_aux, cudaFuncAttributeMaxDynamicSharedMemorySize, SMEM_AUX);

    k_front<<<dim3(NN/32, BB), 256>>>(x, in_w, in_b, ln_w, ln_b,
                                      ow1, ob1, ow2, ob2, mw1, mb1, mw2, mb2);
    k_aux<<<dim3(5, BB), 1024, SMEM_AUX>>>(caw, cab, saw, sab);

    float scale = rsqrtf((float)CC);
    k_gemm3<<<dim3(NN/128, 9, BB), 256, SMEM_G>>>(
        v_w, v_b, q_w, q_b, k_w, k_b, scale);
    k_flash<<<dim3(NKEEP/128, BB), 256, SMEM_F>>>();
    k_dwT<<<dim3(64, BB), 192, SMEM_DW>>>(cs_w, cs_b);
    k_gemmO<<<dim3(NN/128, 3, BB), 256, SMEM_G>>>(out_w, out_b, out);
}